// round 11
// baseline (speedup 1.0000x reference)
#include <cuda_runtime.h>
#include <cstdint>
#include <math.h>

#define Bq 4
#define Hh 16
#define Ss 4096
#define Dd 128
#define Mm 128
#define BH (Bq*Hh)
#define EPSV 1e-6f

// Scratch (zero at first load; every execution re-zeroes g_S/g_w in k_transS)
__device__ float g_S [BH*Dd*Mm];  // S accumulation (WITHOUT S_prev), zero-based
__device__ float g_ST[BH*Dd*Mm];  // S_t transposed [BH, M, D] (tf32 bits)
__device__ float g_w [BH*Dd];     // sum_s phi(k)[s,d] accumulation, zero-based
__device__ float g_w2[BH*Dd];     // final w[d] = Ss*z_prev[d] + g_w[d]

__device__ __forceinline__ float phi(float x) {
    return x > 0.f ? x + 1.f : expf(x);
}
__device__ __forceinline__ unsigned f2tf(float x) {
    unsigned r; asm("cvt.rna.tf32.f32 %0, %1;" : "=r"(r) : "f"(x)); return r;
}
__device__ __forceinline__ unsigned s2u(const void* p) {
    unsigned a;
    asm("{ .reg .u64 t; cvta.to.shared.u64 t, %1; cvt.u32.u64 %0, t; }"
        : "=r"(a) : "l"(p));
    return a;
}
__device__ __forceinline__ void mma8(float* c, const unsigned* a, const unsigned* b) {
    asm volatile(
        "mma.sync.aligned.m16n8k8.row.col.f32.tf32.tf32.f32 "
        "{%0,%1,%2,%3}, {%4,%5,%6,%7}, {%8,%9}, {%0,%1,%2,%3};"
        : "+f"(c[0]), "+f"(c[1]), "+f"(c[2]), "+f"(c[3])
        : "r"(a[0]), "r"(a[1]), "r"(a[2]), "r"(a[3]), "r"(b[0]), "r"(b[1]));
}
__device__ __forceinline__ void ldsm4(unsigned* r, unsigned a) {
    asm volatile("ldmatrix.sync.aligned.m8n8.x4.shared.b16 {%0,%1,%2,%3}, [%4];"
        : "=r"(r[0]), "=r"(r[1]), "=r"(r[2]), "=r"(r[3]) : "r"(a));
}

// ---------------------------------------------------------------------------
// Kernel 1 (512 thr, warp tile 32d x 32m, 32-row stages, XOR-swizzled tiles):
//   g_S += phi(k)^T v ; g_w += sum_s phi(k) ; fused z_t via smem pass
// Staging: warp stages 2 full rows (coalesced LDG), XOR swizzle keeps
// STS <=2-way and LDSM conflict-free.
// tile word(d, s) = d*32 + ((s>>2) ^ (d&7) ^ ((d>>3)&7))*4 + (s&3)
// ---------------------------------------------------------------------------
#define P1_CHUNK 512
#define P1S 32
#define P1NST (P1_CHUNK/P1S)          // 16
#define P1_ARR 4096                   // words per [128][32] tile
#define P1_SMEM_BYTES (4*P1_ARR*4)    // 65536 B

__global__ void __launch_bounds__(512, 1)
k_phase1(const float* __restrict__ kk, const float* __restrict__ vv,
         const float* __restrict__ mask, const float* __restrict__ z_prev,
         float* __restrict__ ztp) {
    extern __shared__ unsigned dyn1[];
    __shared__ float zps[Dd];

    int head = blockIdx.y;
    int sbase = blockIdx.x * P1_CHUNK;
    int tid = threadIdx.x;
    int warp = tid >> 5, lane = tid & 31;
    int gid = lane >> 2, tig = lane & 3;
    int d0w = (warp >> 2) * 32;
    int m0w = (warp & 3) * 32;

    // staging assignment: srow = this thread's s within stage, dbase = 8-wide d block
    int srow = 2 * warp + (lane >> 4);   // 0..31
    int dbase = (lane & 15) * 8;         // 0..120
    int sq = srow >> 2, sl = srow & 3, lx = lane & 7;

    if (tid < Dd) zps[tid] = z_prev[head * Dd + tid];

    // per-lane LDSM constants
    int sel = lane >> 3, lrow = lane & 7;
    int dA1 = d0w + (sel & 1) * 8 + lrow;
    int dA2 = dA1 + 16;
    int cA1 = (dA1 & 7) ^ ((dA1 >> 3) & 7);
    int cA2 = (dA2 & 7) ^ ((dA2 >> 3) & 7);
    int mB1 = m0w + (sel >> 1) * 8 + lrow;
    int mB2 = mB1 + 16;
    int cB1 = (mB1 & 7) ^ ((mB1 >> 3) & 7);
    int cB2 = (mB2 & 7) ^ ((mB2 >> 3) & 7);
    int qA = sel >> 1, qB = sel & 1;
    unsigned kaddr[2] = { s2u(dyn1), s2u(dyn1 + P1_ARR) };
    unsigned vaddr[2] = { s2u(dyn1 + 2 * P1_ARR), s2u(dyn1 + 3 * P1_ARR) };

    float kacc[8];
#pragma unroll
    for (int j = 0; j < 8; j++) kacc[j] = 0.f;
    float acc[2][4][4];
#pragma unroll
    for (int ah = 0; ah < 2; ah++)
#pragma unroll
        for (int bi = 0; bi < 4; bi++)
#pragma unroll
            for (int t = 0; t < 4; t++) acc[ah][bi][t] = 0.f;

    const float* kh = kk + (size_t)head * Ss * Dd;
    const float* vh = vv + (size_t)head * Ss * Mm;
    const float* mh = mask + (size_t)head * Ss;
    float* zth = ztp ? (ztp + (size_t)head * Dd * Ss) : (float*)0;

    float4 kA, kB, vA, vB; float mval;
    {
        int s = sbase + srow;
        kA = *(const float4*)(kh + (size_t)s * Dd + dbase);
        kB = *(const float4*)(kh + (size_t)s * Dd + dbase + 4);
        vA = *(const float4*)(vh + (size_t)s * Mm + dbase);
        vB = *(const float4*)(vh + (size_t)s * Mm + dbase + 4);
        mval = mh[s];
    }
    __syncthreads();   // zps visible

    for (int t = 0; t < P1NST; t++) {
        int b = t & 1;
        unsigned* kb = dyn1 + (b ? P1_ARR : 0);
        unsigned* vb = dyn1 + 2 * P1_ARR + (b ? P1_ARR : 0);
        float kv[8], vvv[8];
        kv[0]=phi(kA.x)*mval; kv[1]=phi(kA.y)*mval; kv[2]=phi(kA.z)*mval; kv[3]=phi(kA.w)*mval;
        kv[4]=phi(kB.x)*mval; kv[5]=phi(kB.y)*mval; kv[6]=phi(kB.z)*mval; kv[7]=phi(kB.w)*mval;
        vvv[0]=vA.x*mval; vvv[1]=vA.y*mval; vvv[2]=vA.z*mval; vvv[3]=vA.w*mval;
        vvv[4]=vB.x*mval; vvv[5]=vB.y*mval; vvv[6]=vB.z*mval; vvv[7]=vB.w*mval;
#pragma unroll
        for (int j = 0; j < 8; j++) {
            kacc[j] += kv[j];
            int w = ((dbase + j) << 5) + ((sq ^ j ^ lx) << 2) + sl;
            kb[w] = f2tf(kv[j]);
            vb[w] = f2tf(vvv[j]);
        }

        if (t + 1 < P1NST) {   // batched coalesced prefetch, hidden by MMA
            int sn = sbase + (t + 1) * P1S + srow;
            kA = *(const float4*)(kh + (size_t)sn * Dd + dbase);
            kB = *(const float4*)(kh + (size_t)sn * Dd + dbase + 4);
            vA = *(const float4*)(vh + (size_t)sn * Mm + dbase);
            vB = *(const float4*)(vh + (size_t)sn * Mm + dbase + 4);
            mval = mh[sn];
        }
        __syncthreads();

        // fused z_t: read back swizzled phi(k), add z_prev, coalesced STG
        if (zth) {
            int dz = tid >> 2, qz = (tid & 3) * 2;
            int cz = (dz & 7) ^ ((dz >> 3) & 7);
            const unsigned* kz = kb + (dz << 5);
            float4 z0 = *(const float4*)(kz + ((qz ^ cz) << 2));
            float4 z1 = *(const float4*)(kz + (((qz + 1) ^ cz) << 2));
            float zp = zps[dz];
            z0.x += zp; z0.y += zp; z0.z += zp; z0.w += zp;
            z1.x += zp; z1.y += zp; z1.z += zp; z1.w += zp;
            float* zr = zth + (size_t)dz * Ss + sbase + t * P1S + qz * 4;
            *(float4*)zr = z0;
            *(float4*)(zr + 4) = z1;
        }

#pragma unroll
        for (int k8 = 0; k8 < P1S; k8 += 8) {
            int q = k8 >> 2;
            unsigned A[2][4], B[2][4];
            ldsm4(A[0], kaddr[b] + (dA1 << 7) + (((q + qA) ^ cA1) << 4));
            ldsm4(A[1], kaddr[b] + (dA2 << 7) + (((q + qA) ^ cA2) << 4));
            ldsm4(B[0], vaddr[b] + (mB1 << 7) + (((q + qB) ^ cB1) << 4));
            ldsm4(B[1], vaddr[b] + (mB2 << 7) + (((q + qB) ^ cB2) << 4));
#pragma unroll
            for (int ah = 0; ah < 2; ah++)
#pragma unroll
                for (int bi = 0; bi < 4; bi++)
                    mma8(acc[ah][bi], A[ah], &B[bi >> 1][(bi & 1) * 2]);
        }
    }

    float* Sg = g_S + (size_t)head * Dd * Mm;
#pragma unroll
    for (int ah = 0; ah < 2; ah++)
#pragma unroll
        for (int bi = 0; bi < 4; bi++) {
            int dr = d0w + ah * 16 + gid;
            int mc = m0w + bi * 8 + tig * 2;
            atomicAdd(&Sg[(size_t)dr * Mm + mc],       acc[ah][bi][0]);
            atomicAdd(&Sg[(size_t)dr * Mm + mc + 1],   acc[ah][bi][1]);
            atomicAdd(&Sg[(size_t)(dr+8) * Mm + mc],   acc[ah][bi][2]);
            atomicAdd(&Sg[(size_t)(dr+8) * Mm + mc+1], acc[ah][bi][3]);
        }
    // combine s-pair within warp, then one atomic per (lane<16, j)
#pragma unroll
    for (int j = 0; j < 8; j++)
        kacc[j] += __shfl_xor_sync(0xffffffffu, kacc[j], 16);
    if (lane < 16) {
#pragma unroll
        for (int j = 0; j < 8; j++)
            atomicAdd(&g_w[head * Dd + dbase + j], kacc[j]);
    }
}

// ---------------------------------------------------------------------------
// Kernel 1b (fused): S_t = g_S + S_prev -> (outS copy, g_ST transposed tf32),
// g_w2 = g_w + Ss*z_prev; re-zero g_S and g_w for next graph replay.
// ---------------------------------------------------------------------------
__global__ void k_transS(const float* __restrict__ S_prev,
                         const float* __restrict__ z_prev,
                         float* __restrict__ outS) {
    __shared__ float tile[32][33];
    int head = blockIdx.z;
    int db = blockIdx.x * 32, mb = blockIdx.y * 32;
    int tx = threadIdx.x, ty = threadIdx.y;   // 32 x 8
    float* Sg = g_S + (size_t)head * Dd * Mm;
    const float* Sp = S_prev + (size_t)head * Dd * Mm;
    float* STg = g_ST + (size_t)head * Dd * Mm;
    float* So = outS ? (outS + (size_t)head * Dd * Mm) : (float*)0;
    for (int r = ty; r < 32; r += 8) {
        size_t idx = (size_t)(db + r) * Mm + mb + tx;
        float val = Sg[idx] + Sp[idx];
        tile[r][tx] = val;
        if (So) So[idx] = val;
        Sg[idx] = 0.f;
    }
    if (blockIdx.x == 0 && blockIdx.y == 0) {
        int tid = ty * 32 + tx;
        if (tid < Dd) {
            g_w2[head * Dd + tid] = g_w[head * Dd + tid]
                                  + (float)Ss * z_prev[head * Dd + tid];
            g_w[head * Dd + tid] = 0.f;
        }
    }
    __syncthreads();
    for (int r = ty; r < 32; r += 8)
        STg[(size_t)(mb + r) * Dd + db + tx] =
            __uint_as_float(f2tf(tile[tx][r]));
}

// ---------------------------------------------------------------------------
// Kernel 2: out = (phi(q) @ S_t) / (phi(q).w + eps)
// grid (2, BH) = 128 CTAs, 512 thr. Resident S_t; q streamed with
// coalesced row-per-warp staging; den via warp reduce.
// ---------------------------------------------------------------------------
#define SQT 2048
#define NCH (SQT/128)
#define PQ 132
#define W_ST   (128*PQ)
#define W_QS   (128*PQ)
#define SM2_WORDS (W_ST + 2*W_QS + 128 + 256)
#define SM2_BYTES (SM2_WORDS * 4)

__global__ void __launch_bounds__(512, 1)
k_phase2(const float* __restrict__ qq, float* __restrict__ out) {
    extern __shared__ unsigned sm2[];
    unsigned (*STs)[PQ] = (unsigned (*)[PQ])sm2;               // [m][d]
    unsigned (*qsb[2])[PQ];
    qsb[0] = (unsigned (*)[PQ])(sm2 + W_ST);
    qsb[1] = (unsigned (*)[PQ])(sm2 + W_ST + W_QS);
    float* ws   = (float*)(sm2 + W_ST + 2 * W_QS);
    float* dens = ws + 128;                                    // [2][128]

    int head = blockIdx.y;
    int sbase = blockIdx.x * SQT;
    int tid = threadIdx.x;
    int warp = tid >> 5, lane = tid & 31;
    int gid = lane >> 2, tig = lane & 3;
    int sw = (warp >> 2) * 32;
    int m0 = (warp & 3) * 32;
    int r4 = tid >> 2, c4 = (tid & 3) * 4;   // S_t prologue only
    int dl = lane * 4;                        // staging d-offset

    const float* qh  = qq + (size_t)head * Ss * Dd;
    const float* STg = g_ST + (size_t)head * Dd * Mm;

#pragma unroll
    for (int i = 0; i < 8; i++) {
        float4 t4 = *(const float4*)(STg + (size_t)r4 * Dd + c4 + i * 16);
        *(float4*)&STs[r4][c4 + i * 16] = t4;
    }
    if (tid < 128) ws[tid] = g_w2[head * Dd + tid];
    __syncthreads();
    float4 wv4 = *(const float4*)(ws + dl);   // per-lane w slice, reused all chunks

    // ---- stage chunk 0 (row-per-warp, coalesced) ----
    {
        const float* qp = qh + (size_t)(sbase + warp) * Dd + dl;
#pragma unroll
        for (int i = 0; i < 8; i++) {
            float4 qa = *(const float4*)(qp + (size_t)(16 * i) * Dd);
            float p0 = phi(qa.x), p1 = phi(qa.y), p2 = phi(qa.z), p3 = phi(qa.w);
            float ds = p0 * wv4.x + p1 * wv4.y + p2 * wv4.z + p3 * wv4.w;
            ds += __shfl_xor_sync(0xffffffffu, ds, 1);
            ds += __shfl_xor_sync(0xffffffffu, ds, 2);
            ds += __shfl_xor_sync(0xffffffffu, ds, 4);
            ds += __shfl_xor_sync(0xffffffffu, ds, 8);
            ds += __shfl_xor_sync(0xffffffffu, ds, 16);
            if (lane == 0) dens[warp + 16 * i] = ds;
            uint4 st; st.x = f2tf(p0); st.y = f2tf(p1);
            st.z = f2tf(p2); st.w = f2tf(p3);
            *(uint4*)&qsb[0][warp + 16 * i][dl] = st;
        }
    }

    int sel = lane >> 3, lrow = lane & 7;
    unsigned aB[2];
#pragma unroll
    for (int b = 0; b < 2; b++)
        aB[b] = s2u(qsb[b]) +
            (((sw + (sel & 1) * 8 + lrow) * PQ + (sel >> 1) * 4) << 2);
    unsigned bB = s2u(STs) +
        (((m0 + (sel >> 1) * 8 + lrow) * PQ + (sel & 1) * 4) << 2);

    for (int c = 0; c < NCH; c++) {
        int cb = c & 1, nb = cb ^ 1;
        bool more = (c + 1 < NCH);

        float4 qn[8];
        if (more) {
            const float* qp = qh + (size_t)(sbase + (c + 1) * 128 + warp) * Dd + dl;
#pragma unroll
            for (int i = 0; i < 8; i++)
                qn[i] = *(const float4*)(qp + (size_t)(16 * i) * Dd);
        }
        __syncthreads();   // qsb[cb], dens[cb] ready

        float acc[2][4][4];
#pragma unroll
        for (int ah = 0; ah < 2; ah++)
#pragma unroll
            for (int bi = 0; bi < 4; bi++)
#pragma unroll
                for (int t = 0; t < 4; t++) acc[ah][bi][t] = 0.f;

#pragma unroll
        for (int i = 0; i < 16; i++) {
            int k0 = i * 8;
            if (more && i >= 8) {   // transform+reduce+store spread over back half
                int j = i - 8;
                float p0 = phi(qn[j].x), p1 = phi(qn[j].y),
                      p2 = phi(qn[j].z), p3 = phi(qn[j].w);
                float ds = p0 * wv4.x + p1 * wv4.y + p2 * wv4.z + p3 * wv4.w;
                ds += __shfl_xor_sync(0xffffffffu, ds, 1);
                ds += __shfl_xor_sync(0xffffffffu, ds, 2);
                ds += __shfl_xor_sync(0xffffffffu, ds, 4);
                ds += __shfl_xor_sync(0xffffffffu, ds, 8);
                ds += __shfl_xor_sync(0xffffffffu, ds, 16);
                if (lane == 0) dens[nb * 128 + warp + 16 * j] = ds;
                uint4 st; st.x = f2tf(p0); st.y = f2tf(p1);
                st.z = f2tf(p2); st.w = f2tf(p3);
                *(uint4*)&qsb[nb][warp + 16 * j][dl] = st;
            }
            unsigned A[2][4], B[2][4];
            ldsm4(A[0], aB[cb] + (k0 << 2));
            ldsm4(A[1], aB[cb] + ((16 * PQ + k0) << 2));
            ldsm4(B[0], bB + (k0 << 2));
            ldsm4(B[1], bB + ((16 * PQ + k0) << 2));
#pragma unroll
            for (int ah = 0; ah < 2; ah++)
#pragma unroll
                for (int bi = 0; bi < 4; bi++)
                    mma8(acc[ah][bi], A[ah], &B[bi >> 1][(bi & 1) * 2]);
        }

        float* oh = out + ((size_t)head * Ss + sbase + c * 128) * Mm;
#pragma unroll
        for (int ah = 0; ah < 2; ah++) {
            int sr = sw + ah * 16 + gid;
            float inv0 = 1.f / (dens[cb * 128 + sr] + EPSV);
            float inv1 = 1.f / (dens[cb * 128 + sr + 8] + EPSV);
#pragma unroll
            for (int bi = 0; bi < 4; bi++) {
                int mc = m0 + bi * 8 + tig * 2;
                float2 r0 = make_float2(acc[ah][bi][0] * inv0, acc[ah][bi][1] * inv0);
                float2 r1 = make_float2(acc[ah][bi][2] * inv1, acc[ah][bi][3] * inv1);
                *(float2*)(oh + (size_t)sr * Mm + mc) = r0;
                *(float2*)(oh + (size_t)(sr + 8) * Mm + mc) = r1;
            }
        }
    }
}

// ---------------------------------------------------------------------------
extern "C" void kernel_launch(void* const* d_in, const int* in_sizes, int n_in,
                              void* d_out, int out_size) {
    (void)in_sizes; (void)n_in;
    const float* q      = (const float*)d_in[0];
    const float* k      = (const float*)d_in[1];
    const float* v      = (const float*)d_in[2];
    const float* mask   = (const float*)d_in[3];
    const float* S_prev = (const float*)d_in[4];
    const float* z_prev = (const float*)d_in[5];
    float* out = (float*)d_out;

    cudaFuncSetAttribute(k_phase1, cudaFuncAttributeMaxDynamicSharedMemorySize,
                         P1_SMEM_BYTES);
    cudaFuncSetAttribute(k_phase2, cudaFuncAttributeMaxDynamicSharedMemorySize,
                         SM2_BYTES);

    const long N_OUT = (long)BH * Ss * Mm;
    const long N_ST  = (long)BH * Dd * Mm;
    const long N_ZT  = (long)BH * Dd * Ss;
    long osz = (long)out_size;
    float* ztp  = (osz >= N_OUT + N_ST + N_ZT) ? (out + N_OUT + N_ST) : (float*)0;
    float* outS = (osz >= N_OUT + N_ST) ? (out + N_OUT) : (float*)0;

    dim3 g1(Ss / P1_CHUNK, BH);
    k_phase1<<<g1, 512, P1_SMEM_BYTES>>>(k, v, mask, z_prev, ztp);

    dim3 gt(Dd / 32, Mm / 32, BH);
    k_transS<<<gt, dim3(32, 8)>>>(S_prev, z_prev, outS);

    dim3 g2(Ss / SQT, BH);
    k_phase2<<<g2, 512, SM2_BYTES>>>(q, out);
}

// round 13
// speedup vs baseline: 1.2514x; 1.2514x over previous
#include <cuda_runtime.h>
#include <cstdint>
#include <math.h>

#define Bq 4
#define Hh 16
#define Ss 4096
#define Dd 128
#define Mm 128
#define BH (Bq*Hh)
#define EPSV 1e-6f

// Scratch (zero at first load; every execution re-zeroes g_S/g_w in k_transS)
__device__ float g_S [BH*Dd*Mm];  // S accumulation (WITHOUT S_prev), zero-based
__device__ float g_ST[BH*Dd*Mm];  // S_t transposed [BH, M, D] (fp32)
__device__ float g_w [BH*Dd];     // sum_s phi(k)[s,d] accumulation, zero-based
__device__ float g_w2[BH*Dd];     // final w[d] = Ss*z_prev[d] + g_w[d]

__device__ __forceinline__ float phi(float x) {
    return x > 0.f ? x + 1.f : expf(x);
}
__device__ __forceinline__ unsigned packh2(float lo, float hi) {
    unsigned r;
    asm("cvt.rn.f16x2.f32 %0, %1, %2;" : "=r"(r) : "f"(hi), "f"(lo));
    return r;
}
__device__ __forceinline__ unsigned s2u(const void* p) {
    unsigned a;
    asm("{ .reg .u64 t; cvta.to.shared.u64 t, %1; cvt.u32.u64 %0, t; }"
        : "=r"(a) : "l"(p));
    return a;
}
__device__ __forceinline__ void mma16(float* c, const unsigned* a,
                                      unsigned b0, unsigned b1) {
    asm volatile(
        "mma.sync.aligned.m16n8k16.row.col.f32.f16.f16.f32 "
        "{%0,%1,%2,%3}, {%4,%5,%6,%7}, {%8,%9}, {%0,%1,%2,%3};"
        : "+f"(c[0]), "+f"(c[1]), "+f"(c[2]), "+f"(c[3])
        : "r"(a[0]), "r"(a[1]), "r"(a[2]), "r"(a[3]), "r"(b0), "r"(b1));
}
__device__ __forceinline__ void ldsm4(unsigned* r, unsigned a) {
    asm volatile("ldmatrix.sync.aligned.m8n8.x4.shared.b16 {%0,%1,%2,%3}, [%4];"
        : "=r"(r[0]), "=r"(r[1]), "=r"(r[2]), "=r"(r[3]) : "r"(a));
}

// ---------------------------------------------------------------------------
// Kernel 1 (fp16 tensor, 512 thr, warp tile 32d x 32m, 32-s stages):
//   g_S += phi(k)^T v ; g_w += sum_s phi(k) ; fused z_t write
// smem row (per d): 16 words k halves | 16 words v halves | 4 pad = 36 words.
// Staging: lane = s; even lanes store packed k words, odd lanes packed v
// words (disjoint bank halves -> conflict-free STS.32).
// ---------------------------------------------------------------------------
#define P1_CHUNK 512
#define P1S 32
#define P1RW 36                        // words per combined row
#define P1BW (128*P1RW)                // words per stage buffer (4608)
#define P1NST (P1_CHUNK/P1S)           // 16
#define P1_SMEM_BYTES (2*P1BW*4)       // 36864 B

__global__ void __launch_bounds__(512, 1)
k_phase1(const float* __restrict__ kk, const float* __restrict__ vv,
         const float* __restrict__ mask, const float* __restrict__ z_prev,
         float* __restrict__ ztp) {
    extern __shared__ unsigned dyn1[];
    __shared__ float zps[Dd];

    int head = blockIdx.y;
    int sbase = blockIdx.x * P1_CHUNK;
    int tid = threadIdx.x;
    int warp = tid >> 5, lane = tid & 31;
    int gid = lane >> 2, tig = lane & 3;
    int d0w = (warp >> 2) * 32;
    int m0w = (warp & 3) * 32;
    int dbase = warp * 8;

    if (tid < Dd) zps[tid] = z_prev[head * Dd + tid];

    // LDSM base byte offsets (within a stage buffer)
    int sel = lane >> 3, lrow = lane & 7;
    int aOffB = 4 * ((d0w + (sel & 1) * 8 + lrow) * P1RW + (sel >> 1) * 4);
    int bOffB = 4 * ((m0w + (sel & 1) * 8 + lrow) * P1RW + 16 + (sel >> 1) * 4);
    unsigned buf0 = s2u(dyn1), buf1 = s2u(dyn1 + P1BW);

    float kacc[8];
#pragma unroll
    for (int j = 0; j < 8; j++) kacc[j] = 0.f;
    float acc[2][4][4];
#pragma unroll
    for (int ah = 0; ah < 2; ah++)
#pragma unroll
        for (int bi = 0; bi < 4; bi++)
#pragma unroll
            for (int t = 0; t < 4; t++) acc[ah][bi][t] = 0.f;

    const float* kh = kk + (size_t)head * Ss * Dd;
    const float* vh = vv + (size_t)head * Ss * Mm;
    const float* mh = mask + (size_t)head * Ss;
    float* zth = ztp ? (ztp + (size_t)head * Dd * Ss) : (float*)0;

    bool evenL = (lane & 1) == 0;
    int s2 = lane >> 1;

    float4 kA, kB, vA, vB; float mval;
    {
        int s = sbase + lane;
        kA = *(const float4*)(kh + (size_t)s * Dd + dbase);
        kB = *(const float4*)(kh + (size_t)s * Dd + dbase + 4);
        vA = *(const float4*)(vh + (size_t)s * Mm + dbase);
        vB = *(const float4*)(vh + (size_t)s * Mm + dbase + 4);
        mval = mh[s];
    }
    __syncthreads();   // zps visible

    for (int t = 0; t < P1NST; t++) {
        int b = t & 1;
        int s = sbase + t * P1S + lane;
        unsigned* stb = dyn1 + (b ? P1BW : 0);
        float kv[8], va[8];
        kv[0]=phi(kA.x)*mval; kv[1]=phi(kA.y)*mval; kv[2]=phi(kA.z)*mval; kv[3]=phi(kA.w)*mval;
        kv[4]=phi(kB.x)*mval; kv[5]=phi(kB.y)*mval; kv[6]=phi(kB.z)*mval; kv[7]=phi(kB.w)*mval;
        va[0]=vA.x*mval; va[1]=vA.y*mval; va[2]=vA.z*mval; va[3]=vA.w*mval;
        va[4]=vB.x*mval; va[5]=vB.y*mval; va[6]=vB.z*mval; va[7]=vB.w*mval;
#pragma unroll
        for (int j = 0; j < 8; j++) {
            kacc[j] += kv[j];
            float kp = __shfl_xor_sync(0xffffffffu, kv[j], 1);
            float vp = __shfl_xor_sync(0xffffffffu, va[j], 1);
            int row = dbase + j;
            if (evenL) {   // own s even: lo = own k, hi = partner k
                stb[row * P1RW + s2] = packh2(kv[j], kp);
            } else {       // own s odd: lo = partner v, hi = own v
                stb[row * P1RW + 16 + s2] = packh2(vp, va[j]);
            }
        }

        if (t + 1 < P1NST) {   // batched coalesced prefetch, hidden by MMA
            int sn = sbase + (t + 1) * P1S + lane;
            kA = *(const float4*)(kh + (size_t)sn * Dd + dbase);
            kB = *(const float4*)(kh + (size_t)sn * Dd + dbase + 4);
            vA = *(const float4*)(vh + (size_t)sn * Mm + dbase);
            vB = *(const float4*)(vh + (size_t)sn * Mm + dbase + 4);
            mval = mh[sn];
        }
        if (zth) {   // fused z_t: coalesced (lanes = consecutive s)
#pragma unroll
            for (int j = 0; j < 8; j++)
                zth[(size_t)(dbase + j) * Ss + s] = kv[j] + zps[dbase + j];
        }
        __syncthreads();

        unsigned base = b ? buf1 : buf0;
#pragma unroll
        for (int ks = 0; ks < 2; ks++) {
            unsigned A[2][4], B[2][4];
            ldsm4(A[0], base + aOffB + ks * 32);
            ldsm4(A[1], base + aOffB + 2304 + ks * 32);   // d+16 (16*36*4)
            ldsm4(B[0], base + bOffB + ks * 32);
            ldsm4(B[1], base + bOffB + 2304 + ks * 32);   // n+16
#pragma unroll
            for (int ah = 0; ah < 2; ah++)
#pragma unroll
                for (int bi = 0; bi < 4; bi++)
                    mma16(acc[ah][bi], A[ah],
                          B[bi >> 1][bi & 1], B[bi >> 1][(bi & 1) + 2]);
        }
    }

    float* Sg = g_S + (size_t)head * Dd * Mm;
#pragma unroll
    for (int ah = 0; ah < 2; ah++)
#pragma unroll
        for (int bi = 0; bi < 4; bi++) {
            int dr = d0w + ah * 16 + gid;
            int mc = m0w + bi * 8 + tig * 2;
            atomicAdd(&Sg[(size_t)dr * Mm + mc],       acc[ah][bi][0]);
            atomicAdd(&Sg[(size_t)dr * Mm + mc + 1],   acc[ah][bi][1]);
            atomicAdd(&Sg[(size_t)(dr+8) * Mm + mc],   acc[ah][bi][2]);
            atomicAdd(&Sg[(size_t)(dr+8) * Mm + mc+1], acc[ah][bi][3]);
        }
#pragma unroll
    for (int j = 0; j < 8; j++) {
        kacc[j] += __shfl_xor_sync(0xffffffffu, kacc[j], 1);
        kacc[j] += __shfl_xor_sync(0xffffffffu, kacc[j], 2);
        kacc[j] += __shfl_xor_sync(0xffffffffu, kacc[j], 4);
        kacc[j] += __shfl_xor_sync(0xffffffffu, kacc[j], 8);
        kacc[j] += __shfl_xor_sync(0xffffffffu, kacc[j], 16);
    }
    if (lane == 0) {
#pragma unroll
        for (int j = 0; j < 8; j++)
            atomicAdd(&g_w[head * Dd + dbase + j], kacc[j]);
    }
}

// ---------------------------------------------------------------------------
// Kernel 1b: S_t = g_S + S_prev -> (outS copy, g_ST transposed fp32),
// g_w2 = g_w + Ss*z_prev; re-zero g_S/g_w for next replay.
// ---------------------------------------------------------------------------
__global__ void k_transS(const float* __restrict__ S_prev,
                         const float* __restrict__ z_prev,
                         float* __restrict__ outS) {
    __shared__ float tile[32][33];
    int head = blockIdx.z;
    int db = blockIdx.x * 32, mb = blockIdx.y * 32;
    int tx = threadIdx.x, ty = threadIdx.y;
    float* Sg = g_S + (size_t)head * Dd * Mm;
    const float* Sp = S_prev + (size_t)head * Dd * Mm;
    float* STg = g_ST + (size_t)head * Dd * Mm;
    float* So = outS ? (outS + (size_t)head * Dd * Mm) : (float*)0;
    for (int r = ty; r < 32; r += 8) {
        size_t idx = (size_t)(db + r) * Mm + mb + tx;
        float val = Sg[idx] + Sp[idx];
        tile[r][tx] = val;
        if (So) So[idx] = val;
        Sg[idx] = 0.f;
    }
    if (blockIdx.x == 0 && blockIdx.y == 0) {
        int tid = ty * 32 + tx;
        if (tid < Dd) {
            g_w2[head * Dd + tid] = g_w[head * Dd + tid]
                                  + (float)Ss * z_prev[head * Dd + tid];
            g_w[head * Dd + tid] = 0.f;
        }
    }
    __syncthreads();
    for (int r = ty; r < 32; r += 8)
        STg[(size_t)(mb + r) * Dd + db + tx] = tile[tx][r];
}

// ---------------------------------------------------------------------------
// Kernel 2 (fp16 tensor): out = (phi(q) @ S_t) / (phi(q).w + eps)
// grid (2, BH) = 128 CTAs, 512 thr. Resident S_t^T (halves, pitch 68);
// q streamed (double buffer), batched prefetch, dens in fp32.
// ---------------------------------------------------------------------------
#define SQT 2048
#define NCH (SQT/128)
#define P2RW 68                        // words per row (64 data + 4 pad)
#define P2BW (128*P2RW)                // 8704 words per tile
#define OFF_WS   (3*P2BW)
#define OFF_DENS (OFF_WS + 128)
#define SM2_WORDS (OFF_DENS + 256)
#define SM2_BYTES (SM2_WORDS * 4)

__global__ void __launch_bounds__(512, 1)
k_phase2(const float* __restrict__ qq, float* __restrict__ out) {
    extern __shared__ unsigned sm2[];
    unsigned* Ab[2] = { sm2, sm2 + P2BW };
    unsigned* Bb = sm2 + 2 * P2BW;
    float* ws   = (float*)(sm2 + OFF_WS);
    float* dens = (float*)(sm2 + OFF_DENS);   // [2][128]

    int head = blockIdx.y;
    int sbase = blockIdx.x * SQT;
    int tid = threadIdx.x;
    int warp = tid >> 5, lane = tid & 31;
    int gid = lane >> 2, tig = lane & 3;
    int sw = (warp >> 2) * 32;
    int m0 = (warp & 3) * 32;

    const float* qh  = qq + (size_t)head * Ss * Dd;
    const float* STg = g_ST + (size_t)head * Dd * Mm;

    if (tid < 128) ws[tid] = g_w2[head * Dd + tid];
    // stage B (S_t^T as halves): row m = warp+16i, lane covers d = 4*lane
    {
        const float* bp = STg + (size_t)warp * Dd + lane * 4;
#pragma unroll
        for (int i = 0; i < 8; i++) {
            float4 t4 = *(const float4*)(bp + (size_t)(16 * i) * Dd);
            int r = warp + 16 * i;
            unsigned* w = Bb + r * P2RW + lane * 2;
            w[0] = packh2(t4.x, t4.y);
            w[1] = packh2(t4.z, t4.w);
        }
    }
    __syncthreads();   // ws visible for staging below
    float4 wv4 = *(const float4*)(ws + lane * 4);

    // stage A chunk 0 + dens[0]
    {
        const float* qp = qh + (size_t)(sbase + warp) * Dd + lane * 4;
#pragma unroll
        for (int i = 0; i < 8; i++) {
            float4 qa = *(const float4*)(qp + (size_t)(16 * i) * Dd);
            float p0 = phi(qa.x), p1 = phi(qa.y), p2 = phi(qa.z), p3 = phi(qa.w);
            float ds = p0 * wv4.x + p1 * wv4.y + p2 * wv4.z + p3 * wv4.w;
            ds += __shfl_xor_sync(0xffffffffu, ds, 1);
            ds += __shfl_xor_sync(0xffffffffu, ds, 2);
            ds += __shfl_xor_sync(0xffffffffu, ds, 4);
            ds += __shfl_xor_sync(0xffffffffu, ds, 8);
            ds += __shfl_xor_sync(0xffffffffu, ds, 16);
            int r = warp + 16 * i;
            if (lane == 0) dens[r] = ds;
            unsigned* w = Ab[0] + r * P2RW + lane * 2;
            w[0] = packh2(p0, p1);
            w[1] = packh2(p2, p3);
        }
    }

    // LDSM base byte offsets
    int sel = lane >> 3, lrow = lane & 7;
    int aOffB = 4 * ((sw + (sel & 1) * 8 + lrow) * P2RW + (sel >> 1) * 4);
    int bOffB = 4 * ((m0 + (sel & 1) * 8 + lrow) * P2RW + (sel >> 1) * 4);
    unsigned aBase[2] = { s2u(Ab[0]), s2u(Ab[1]) };
    unsigned bBase = s2u(Bb);
    const int ROW16 = 16 * P2RW * 4;   // byte offset of +16 rows

    for (int c = 0; c < NCH; c++) {
        int cb = c & 1, nb = cb ^ 1;
        bool more = (c + 1 < NCH);

        float4 qn[8];
        if (more) {
            const float* qp = qh + (size_t)(sbase + (c + 1) * 128 + warp) * Dd + lane * 4;
#pragma unroll
            for (int i = 0; i < 8; i++)
                qn[i] = *(const float4*)(qp + (size_t)(16 * i) * Dd);
        }
        __syncthreads();   // A[cb], dens[cb] ready

        float acc[2][4][4];
#pragma unroll
        for (int ah = 0; ah < 2; ah++)
#pragma unroll
            for (int bi = 0; bi < 4; bi++)
#pragma unroll
                for (int t = 0; t < 4; t++) acc[ah][bi][t] = 0.f;

#pragma unroll
        for (int i = 0; i < 8; i++) {          // 8 k16 steps over d=128
            if (more && i >= 4) {              // stage 2 rows per back-half iter
#pragma unroll
                for (int h = 0; h < 2; h++) {
                    int j = (i - 4) * 2 + h;
                    float p0 = phi(qn[j].x), p1 = phi(qn[j].y),
                          p2 = phi(qn[j].z), p3 = phi(qn[j].w);
                    float ds = p0 * wv4.x + p1 * wv4.y + p2 * wv4.z + p3 * wv4.w;
                    ds += __shfl_xor_sync(0xffffffffu, ds, 1);
                    ds += __shfl_xor_sync(0xffffffffu, ds, 2);
                    ds += __shfl_xor_sync(0xffffffffu, ds, 4);
                    ds += __shfl_xor_sync(0xffffffffu, ds, 8);
                    ds += __shfl_xor_sync(0xffffffffu, ds, 16);
                    int r = warp + 16 * j;
                    if (lane == 0) dens[nb * 128 + r] = ds;
                    unsigned* w = Ab[nb] + r * P2RW + lane * 2;
                    w[0] = packh2(p0, p1);
                    w[1] = packh2(p2, p3);
                }
            }
            unsigned A[2][4], B[2][4];
            ldsm4(A[0], aBase[cb] + aOffB + i * 32);
            ldsm4(A[1], aBase[cb] + aOffB + ROW16 + i * 32);
            ldsm4(B[0], bBase + bOffB + i * 32);
            ldsm4(B[1], bBase + bOffB + ROW16 + i * 32);
#pragma unroll
            for (int ah = 0; ah < 2; ah++)
#pragma unroll
                for (int bi = 0; bi < 4; bi++)
                    mma16(acc[ah][bi], A[ah],
                          B[bi >> 1][bi & 1], B[bi >> 1][(bi & 1) + 2]);
        }

        float* oh = out + ((size_t)head * Ss + sbase + c * 128) * Mm;
#pragma unroll
        for (int ah = 0; ah < 2; ah++) {
            int sr = sw + ah * 16 + gid;
            float inv0 = 1.f / (dens[cb * 128 + sr] + EPSV);
            float inv1 = 1.f / (dens[cb * 128 + sr + 8] + EPSV);
#pragma unroll
            for (int bi = 0; bi < 4; bi++) {
                int mc = m0 + bi * 8 + tig * 2;
                float2 r0 = make_float2(acc[ah][bi][0] * inv0, acc[ah][bi][1] * inv0);
                float2 r1 = make_float2(acc[ah][bi][2] * inv1, acc[ah][bi][3] * inv1);
                *(float2*)(oh + (size_t)sr * Mm + mc) = r0;
                *(float2*)(oh + (size_t)(sr + 8) * Mm + mc) = r1;
            }
        }
    }
}

// ---------------------------------------------------------------------------
extern "C" void kernel_launch(void* const* d_in, const int* in_sizes, int n_in,
                              void* d_out, int out_size) {
    (void)in_sizes; (void)n_in;
    const float* q      = (const float*)d_in[0];
    const float* k      = (const float*)d_in[1];
    const float* v      = (const float*)d_in[2];
    const float* mask   = (const float*)d_in[3];
    const float* S_prev = (const float*)d_in[4];
    const float* z_prev = (const float*)d_in[5];
    float* out = (float*)d_out;

    cudaFuncSetAttribute(k_phase1, cudaFuncAttributeMaxDynamicSharedMemorySize,
                         P1_SMEM_BYTES);
    cudaFuncSetAttribute(k_phase2, cudaFuncAttributeMaxDynamicSharedMemorySize,
                         SM2_BYTES);

    const long N_OUT = (long)BH * Ss * Mm;
    const long N_ST  = (long)BH * Dd * Mm;
    const long N_ZT  = (long)BH * Dd * Ss;
    long osz = (long)out_size;
    float* ztp  = (osz >= N_OUT + N_ST + N_ZT) ? (out + N_OUT + N_ST) : (float*)0;
    float* outS = (osz >= N_OUT + N_ST) ? (out + N_OUT) : (float*)0;

    dim3 g1(Ss / P1_CHUNK, BH);
    k_phase1<<<g1, 512, P1_SMEM_BYTES>>>(k, v, mask, z_prev, ztp);

    dim3 gt(Dd / 32, Mm / 32, BH);
    k_transS<<<gt, dim3(32, 8)>>>(S_prev, z_prev, outS);

    dim3 g2(Ss / SQT, BH);
    k_phase2<<<g2, 512, SM2_BYTES>>>(q, out);
}

// round 14
// speedup vs baseline: 1.2644x; 1.0104x over previous
#include <cuda_runtime.h>
#include <cuda_fp16.h>
#include <cstdint>
#include <math.h>

#define Bq 4
#define Hh 16
#define Ss 4096
#define Dd 128
#define Mm 128
#define BH (Bq*Hh)
#define EPSV 1e-6f

// Scratch (zero at first load; every execution re-zeroes g_S/g_w in k_transS)
__device__ float g_S [BH*Dd*Mm];  // S accumulation (WITHOUT S_prev), zero-based
__device__ float g_ST[BH*Dd*Mm];  // S_t transposed [BH, M, D] (fp32)
__device__ float g_w [BH*Dd];     // sum_s phi(k)[s,d] accumulation, zero-based
__device__ float g_w2[BH*Dd];     // final w[d] = Ss*z_prev[d] + g_w[d]

__device__ __forceinline__ float phi(float x) {
    return x > 0.f ? x + 1.f : expf(x);
}
__device__ __forceinline__ unsigned packh2(float lo, float hi) {
    unsigned r;
    asm("cvt.rn.f16x2.f32 %0, %1, %2;" : "=r"(r) : "f"(hi), "f"(lo));
    return r;
}
__device__ __forceinline__ unsigned s2u(const void* p) {
    unsigned a;
    asm("{ .reg .u64 t; cvta.to.shared.u64 t, %1; cvt.u32.u64 %0, t; }"
        : "=r"(a) : "l"(p));
    return a;
}
__device__ __forceinline__ void mma16(float* c, const unsigned* a,
                                      unsigned b0, unsigned b1) {
    asm volatile(
        "mma.sync.aligned.m16n8k16.row.col.f32.f16.f16.f32 "
        "{%0,%1,%2,%3}, {%4,%5,%6,%7}, {%8,%9}, {%0,%1,%2,%3};"
        : "+f"(c[0]), "+f"(c[1]), "+f"(c[2]), "+f"(c[3])
        : "r"(a[0]), "r"(a[1]), "r"(a[2]), "r"(a[3]), "r"(b0), "r"(b1));
}
__device__ __forceinline__ void ldsm4(unsigned* r, unsigned a) {
    asm volatile("ldmatrix.sync.aligned.m8n8.x4.shared.b16 {%0,%1,%2,%3}, [%4];"
        : "=r"(r[0]), "=r"(r[1]), "=r"(r[2]), "=r"(r[3]) : "r"(a));
}
__device__ __forceinline__ void ldsm4t(unsigned* r, unsigned a) {
    asm volatile("ldmatrix.sync.aligned.m8n8.x4.trans.shared.b16 {%0,%1,%2,%3}, [%4];"
        : "=r"(r[0]), "=r"(r[1]), "=r"(r[2]), "=r"(r[3]) : "r"(a));
}

// ---------------------------------------------------------------------------
// Kernel 1 (fp16 tensor + ldmatrix.trans, 512 thr, warp tile 32d x 32m):
//   g_S += phi(k)^T v ; g_w += sum_s phi(k) ; fused z_t via smem read-back
// Tiles stored s-major [32 s][128 d halves], pitch 68 words (272B):
//   - staging LDG coalesced (warp = 2 full rows), shfl-free h2 pack, STS.128
//   - MMA operands via ldmatrix.x4.trans (conflict-free at pitch 68)
// ---------------------------------------------------------------------------
#define P1_CHUNK 512
#define P1S 32
#define P1P 68                          // words per s-row
#define TW (P1S*P1P)                    // 2176 words per tile
#define P1NST (P1_CHUNK/P1S)            // 16
#define P1_SMEM_BYTES (4*TW*4)          // 34816 B (k0,v0,k1,v1)

__global__ void __launch_bounds__(512, 1)
k_phase1(const float* __restrict__ kk, const float* __restrict__ vv,
         const float* __restrict__ mask, const float* __restrict__ z_prev,
         float* __restrict__ ztp) {
    extern __shared__ unsigned dyn1[];
    __shared__ float zps[Dd];
    __shared__ float ksum_sm[P1S][Dd];   // 16 KB

    int head = blockIdx.y;
    int sbase = blockIdx.x * P1_CHUNK;
    int tid = threadIdx.x;
    int warp = tid >> 5, lane = tid & 31;
    int gid = lane >> 2, tig = lane & 3;
    int d0w = (warp >> 2) * 32;
    int m0w = (warp & 3) * 32;
    int srow = tid >> 4;                 // 0..31 (warp covers 2 rows)
    int dcol = (tid & 15) * 8;           // 8 d per thread

    if (tid < Dd) zps[tid] = z_prev[head * Dd + tid];

    // ldmatrix.trans per-lane byte offsets within a tile
    int lrow = (lane & 7) + ((lane >> 4) & 1) * 8;     // s-row within 16-block
    int csel = ((lane >> 3) & 1) * 16;                 // +8 halves (d or m)
    int aOffB = lrow * (P1P * 4) + d0w * 2 + csel;
    int bOffB = lrow * (P1P * 4) + m0w * 2 + csel;
    unsigned kbase[2] = { s2u(dyn1), s2u(dyn1 + 2 * TW) };
    unsigned vbase[2] = { s2u(dyn1 + TW), s2u(dyn1 + 3 * TW) };

    float kacc[8];
#pragma unroll
    for (int j = 0; j < 8; j++) kacc[j] = 0.f;
    float acc[2][4][4];
#pragma unroll
    for (int ah = 0; ah < 2; ah++)
#pragma unroll
        for (int bi = 0; bi < 4; bi++)
#pragma unroll
            for (int t = 0; t < 4; t++) acc[ah][bi][t] = 0.f;

    const float* kh = kk + (size_t)head * Ss * Dd;
    const float* vh = vv + (size_t)head * Ss * Mm;
    const float* mh = mask + (size_t)head * Ss;
    float* zth = ztp ? (ztp + (size_t)head * Dd * Ss) : (float*)0;

    float4 kA, kB, vA, vB; float mval;
    {
        int s = sbase + srow;
        kA = *(const float4*)(kh + (size_t)s * Dd + dcol);
        kB = *(const float4*)(kh + (size_t)s * Dd + dcol + 4);
        vA = *(const float4*)(vh + (size_t)s * Mm + dcol);
        vB = *(const float4*)(vh + (size_t)s * Mm + dcol + 4);
        mval = mh[s];
    }

    for (int t = 0; t < P1NST; t++) {
        int b = t & 1;
        unsigned* kb = dyn1 + b * 2 * TW;
        unsigned* vb = kb + TW;
        float kv[8], va[8];
        kv[0]=phi(kA.x)*mval; kv[1]=phi(kA.y)*mval; kv[2]=phi(kA.z)*mval; kv[3]=phi(kA.w)*mval;
        kv[4]=phi(kB.x)*mval; kv[5]=phi(kB.y)*mval; kv[6]=phi(kB.z)*mval; kv[7]=phi(kB.w)*mval;
        va[0]=vA.x*mval; va[1]=vA.y*mval; va[2]=vA.z*mval; va[3]=vA.w*mval;
        va[4]=vB.x*mval; va[5]=vB.y*mval; va[6]=vB.z*mval; va[7]=vB.w*mval;
#pragma unroll
        for (int j = 0; j < 8; j++) kacc[j] += kv[j];
        {
            uint4 kp = make_uint4(packh2(kv[0], kv[1]), packh2(kv[2], kv[3]),
                                  packh2(kv[4], kv[5]), packh2(kv[6], kv[7]));
            uint4 vp = make_uint4(packh2(va[0], va[1]), packh2(va[2], va[3]),
                                  packh2(va[4], va[5]), packh2(va[6], va[7]));
            *(uint4*)&kb[srow * P1P + (tid & 15) * 4] = kp;
            *(uint4*)&vb[srow * P1P + (tid & 15) * 4] = vp;
        }

        if (t + 1 < P1NST) {   // batched coalesced prefetch, hidden by MMA
            int sn = sbase + (t + 1) * P1S + srow;
            kA = *(const float4*)(kh + (size_t)sn * Dd + dcol);
            kB = *(const float4*)(kh + (size_t)sn * Dd + dcol + 4);
            vA = *(const float4*)(vh + (size_t)sn * Mm + dcol);
            vB = *(const float4*)(vh + (size_t)sn * Mm + dcol + 4);
            mval = mh[sn];
        }
        __syncthreads();

        // fused z_t: transposed smem read-back, coalesced STG.128
        if (zth) {
            int dz = tid >> 2, szb = (tid & 3) * 8;
            const __half* khp = (const __half*)kb;
            float zf[8]; float zp = zps[dz];
#pragma unroll
            for (int i = 0; i < 8; i++)
                zf[i] = __half2float(khp[(szb + i) * (P1P * 2) + dz]) + zp;
            float* zr = zth + (size_t)dz * Ss + sbase + t * P1S + szb;
            *(float4*)zr       = make_float4(zf[0], zf[1], zf[2], zf[3]);
            *(float4*)(zr + 4) = make_float4(zf[4], zf[5], zf[6], zf[7]);
        }

#pragma unroll
        for (int ks = 0; ks < 2; ks++) {
            int so = ks * 16 * P1P * 4;
            unsigned A0[4], A1[4], B0[4], B1[4];
            ldsm4t(A0, kbase[b] + aOffB + so);
            ldsm4t(A1, kbase[b] + aOffB + so + 32);   // d+16
            ldsm4t(B0, vbase[b] + bOffB + so);
            ldsm4t(B1, vbase[b] + bOffB + so + 32);   // m+16
#pragma unroll
            for (int ah = 0; ah < 2; ah++) {
                const unsigned* Aa = ah ? A1 : A0;
#pragma unroll
                for (int bi = 0; bi < 4; bi++) {
                    const unsigned* Bl = (bi >> 1) ? B1 : B0;
                    mma16(acc[ah][bi], Aa, Bl[bi & 1], Bl[(bi & 1) + 2]);
                }
            }
        }
    }

    float* Sg = g_S + (size_t)head * Dd * Mm;
#pragma unroll
    for (int ah = 0; ah < 2; ah++)
#pragma unroll
        for (int bi = 0; bi < 4; bi++) {
            int dr = d0w + ah * 16 + gid;
            int mc = m0w + bi * 8 + tig * 2;
            atomicAdd(&Sg[(size_t)dr * Mm + mc],       acc[ah][bi][0]);
            atomicAdd(&Sg[(size_t)dr * Mm + mc + 1],   acc[ah][bi][1]);
            atomicAdd(&Sg[(size_t)(dr+8) * Mm + mc],   acc[ah][bi][2]);
            atomicAdd(&Sg[(size_t)(dr+8) * Mm + mc+1], acc[ah][bi][3]);
        }

    // ksum: smem column reduction, one atomic per d per CTA
#pragma unroll
    for (int j = 0; j < 8; j++) ksum_sm[srow][dcol + j] = kacc[j];
    __syncthreads();
    if (tid < Dd) {
        float s = 0.f;
#pragma unroll 8
        for (int i = 0; i < P1S; i++) s += ksum_sm[i][tid];
        atomicAdd(&g_w[head * Dd + tid], s);
    }
}

// ---------------------------------------------------------------------------
// Kernel 1b: S_t = g_S + S_prev -> (outS copy, g_ST transposed fp32),
// g_w2 = g_w + Ss*z_prev; re-zero g_S/g_w for next replay.
// ---------------------------------------------------------------------------
__global__ void k_transS(const float* __restrict__ S_prev,
                         const float* __restrict__ z_prev,
                         float* __restrict__ outS) {
    __shared__ float tile[32][33];
    int head = blockIdx.z;
    int db = blockIdx.x * 32, mb = blockIdx.y * 32;
    int tx = threadIdx.x, ty = threadIdx.y;
    float* Sg = g_S + (size_t)head * Dd * Mm;
    const float* Sp = S_prev + (size_t)head * Dd * Mm;
    float* STg = g_ST + (size_t)head * Dd * Mm;
    float* So = outS ? (outS + (size_t)head * Dd * Mm) : (float*)0;
    for (int r = ty; r < 32; r += 8) {
        size_t idx = (size_t)(db + r) * Mm + mb + tx;
        float val = Sg[idx] + Sp[idx];
        tile[r][tx] = val;
        if (So) So[idx] = val;
        Sg[idx] = 0.f;
    }
    if (blockIdx.x == 0 && blockIdx.y == 0) {
        int tid = ty * 32 + tx;
        if (tid < Dd) {
            g_w2[head * Dd + tid] = g_w[head * Dd + tid]
                                  + (float)Ss * z_prev[head * Dd + tid];
            g_w[head * Dd + tid] = 0.f;
        }
    }
    __syncthreads();
    for (int r = ty; r < 32; r += 8)
        STg[(size_t)(mb + r) * Dd + db + tx] = tile[tx][r];
}

// ---------------------------------------------------------------------------
// Kernel 2 (fp16 tensor, unchanged from R13): out = (phi(q)@S_t)/(phi(q).w+eps)
// ---------------------------------------------------------------------------
#define SQT 2048
#define NCH (SQT/128)
#define P2RW 68
#define P2BW (128*P2RW)
#define OFF_WS   (3*P2BW)
#define OFF_DENS (OFF_WS + 128)
#define SM2_WORDS (OFF_DENS + 256)
#define SM2_BYTES (SM2_WORDS * 4)

__global__ void __launch_bounds__(512, 1)
k_phase2(const float* __restrict__ qq, float* __restrict__ out) {
    extern __shared__ unsigned sm2[];
    unsigned* Ab[2] = { sm2, sm2 + P2BW };
    unsigned* Bb = sm2 + 2 * P2BW;
    float* ws   = (float*)(sm2 + OFF_WS);
    float* dens = (float*)(sm2 + OFF_DENS);   // [2][128]

    int head = blockIdx.y;
    int sbase = blockIdx.x * SQT;
    int tid = threadIdx.x;
    int warp = tid >> 5, lane = tid & 31;
    int gid = lane >> 2, tig = lane & 3;
    int sw = (warp >> 2) * 32;
    int m0 = (warp & 3) * 32;

    const float* qh  = qq + (size_t)head * Ss * Dd;
    const float* STg = g_ST + (size_t)head * Dd * Mm;

    if (tid < 128) ws[tid] = g_w2[head * Dd + tid];
    {
        const float* bp = STg + (size_t)warp * Dd + lane * 4;
#pragma unroll
        for (int i = 0; i < 8; i++) {
            float4 t4 = *(const float4*)(bp + (size_t)(16 * i) * Dd);
            int r = warp + 16 * i;
            unsigned* w = Bb + r * P2RW + lane * 2;
            w[0] = packh2(t4.x, t4.y);
            w[1] = packh2(t4.z, t4.w);
        }
    }
    __syncthreads();
    float4 wv4 = *(const float4*)(ws + lane * 4);

    {
        const float* qp = qh + (size_t)(sbase + warp) * Dd + lane * 4;
#pragma unroll
        for (int i = 0; i < 8; i++) {
            float4 qa = *(const float4*)(qp + (size_t)(16 * i) * Dd);
            float p0 = phi(qa.x), p1 = phi(qa.y), p2 = phi(qa.z), p3 = phi(qa.w);
            float ds = p0 * wv4.x + p1 * wv4.y + p2 * wv4.z + p3 * wv4.w;
            ds += __shfl_xor_sync(0xffffffffu, ds, 1);
            ds += __shfl_xor_sync(0xffffffffu, ds, 2);
            ds += __shfl_xor_sync(0xffffffffu, ds, 4);
            ds += __shfl_xor_sync(0xffffffffu, ds, 8);
            ds += __shfl_xor_sync(0xffffffffu, ds, 16);
            int r = warp + 16 * i;
            if (lane == 0) dens[r] = ds;
            unsigned* w = Ab[0] + r * P2RW + lane * 2;
            w[0] = packh2(p0, p1);
            w[1] = packh2(p2, p3);
        }
    }

    int sel = lane >> 3, lrow = lane & 7;
    int aOffB = 4 * ((sw + (sel & 1) * 8 + lrow) * P2RW + (sel >> 1) * 4);
    int bOffB = 4 * ((m0 + (sel & 1) * 8 + lrow) * P2RW + (sel >> 1) * 4);
    unsigned aBase[2] = { s2u(Ab[0]), s2u(Ab[1]) };
    unsigned bBase = s2u(Bb);
    const int ROW16 = 16 * P2RW * 4;

    for (int c = 0; c < NCH; c++) {
        int cb = c & 1, nb = cb ^ 1;
        bool more = (c + 1 < NCH);

        float4 qn[8];
        if (more) {
            const float* qp = qh + (size_t)(sbase + (c + 1) * 128 + warp) * Dd + lane * 4;
#pragma unroll
            for (int i = 0; i < 8; i++)
                qn[i] = *(const float4*)(qp + (size_t)(16 * i) * Dd);
        }
        __syncthreads();

        float acc[2][4][4];
#pragma unroll
        for (int ah = 0; ah < 2; ah++)
#pragma unroll
            for (int bi = 0; bi < 4; bi++)
#pragma unroll
                for (int t = 0; t < 4; t++) acc[ah][bi][t] = 0.f;

#pragma unroll
        for (int i = 0; i < 8; i++) {
            if (more && i >= 4) {
#pragma unroll
                for (int h = 0; h < 2; h++) {
                    int j = (i - 4) * 2 + h;
                    float p0 = phi(qn[j].x), p1 = phi(qn[j].y),
                          p2 = phi(qn[j].z), p3 = phi(qn[j].w);
                    float ds = p0 * wv4.x + p1 * wv4.y + p2 * wv4.z + p3 * wv4.w;
                    ds += __shfl_xor_sync(0xffffffffu, ds, 1);
                    ds += __shfl_xor_sync(0xffffffffu, ds, 2);
                    ds += __shfl_xor_sync(0xffffffffu, ds, 4);
                    ds += __shfl_xor_sync(0xffffffffu, ds, 8);
                    ds += __shfl_xor_sync(0xffffffffu, ds, 16);
                    int r = warp + 16 * j;
                    if (lane == 0) dens[nb * 128 + r] = ds;
                    unsigned* w = Ab[nb] + r * P2RW + lane * 2;
                    w[0] = packh2(p0, p1);
                    w[1] = packh2(p2, p3);
                }
            }
            unsigned A[2][4], B[2][4];
            ldsm4(A[0], aBase[cb] + aOffB + i * 32);
            ldsm4(A[1], aBase[cb] + aOffB + ROW16 + i * 32);
            ldsm4(B[0], bBase + bOffB + i * 32);
            ldsm4(B[1], bBase + bOffB + ROW16 + i * 32);
#pragma unroll
            for (int ah = 0; ah < 2; ah++)
#pragma unroll
                for (int bi = 0; bi < 4; bi++)
                    mma16(acc[ah][bi], A[ah],
                          B[bi >> 1][bi & 1], B[bi >> 1][(bi & 1) + 2]);
        }

        float* oh = out + ((size_t)head * Ss + sbase + c * 128) * Mm;
#pragma unroll
        for (int ah = 0; ah < 2; ah++) {
            int sr = sw + ah * 16 + gid;
            float inv0 = 1.f / (dens[cb * 128 + sr] + EPSV);
            float inv1 = 1.f / (dens[cb * 128 + sr + 8] + EPSV);
#pragma unroll
            for (int bi = 0; bi < 4; bi++) {
                int mc = m0 + bi * 8 + tig * 2;
                float2 r0 = make_float2(acc[ah][bi][0] * inv0, acc[ah][bi][1] * inv0);
                float2 r1 = make_float2(acc[ah][bi][2] * inv1, acc[ah][bi][3] * inv1);
                *(float2*)(oh + (size_t)sr * Mm + mc) = r0;
                *(float2*)(oh + (size_t)(sr + 8) * Mm + mc) = r1;
            }
        }
    }
}

// ---------------------------------------------------------------------------
extern "C" void kernel_launch(void* const* d_in, const int* in_sizes, int n_in,
                              void* d_out, int out_size) {
    (void)in_sizes; (void)n_in;
    const float* q      = (const float*)d_in[0];
    const float* k      = (const float*)d_in[1];
    const float* v      = (const float*)d_in[2];
    const float* mask   = (const float*)d_in[3];
    const float* S_prev = (const float*)d_in[4];
    const float* z_prev = (const float*)d_in[5];
    float* out = (float*)d_out;

    cudaFuncSetAttribute(k_phase1, cudaFuncAttributeMaxDynamicSharedMemorySize,
                         P1_SMEM_BYTES);
    cudaFuncSetAttribute(k_phase2, cudaFuncAttributeMaxDynamicSharedMemorySize,
                         SM2_BYTES);

    const long N_OUT = (long)BH * Ss * Mm;
    const long N_ST  = (long)BH * Dd * Mm;
    const long N_ZT  = (long)BH * Dd * Ss;
    long osz = (long)out_size;
    float* ztp  = (osz >= N_OUT + N_ST + N_ZT) ? (out + N_OUT + N_ST) : (float*)0;
    float* outS = (osz >= N_OUT + N_ST) ? (out + N_OUT) : (float*)0;

    dim3 g1(Ss / P1_CHUNK, BH);
    k_phase1<<<g1, 512, P1_SMEM_BYTES>>>(k, v, mask, z_prev, ztp);

    dim3 gt(Dd / 32, Mm / 32, BH);
    k_transS<<<gt, dim3(32, 8)>>>(S_prev, z_prev, outS);

    dim3 g2(Ss / SQT, BH);
    k_phase2<<<g2, 512, SM2_BYTES>>>(q, out);
}